// round 5
// baseline (speedup 1.0000x reference)
#include <cuda_runtime.h>
#include <cstdint>

// ---------------------------------------------------------------------------
// Problem constants
// ---------------------------------------------------------------------------
static constexpr int M = 65536;
static constexpr int K = 512;
static constexpr int N = 512;

static constexpr int BM      = 64;       // CTA M tile
static constexpr int BK      = 128;      // K bytes per chunk
static constexpr int CHUNKS  = K / BK;   // 4
static constexpr int THREADS = 512;      // 16 warps: 2 (M) x 8 (N)

// Shared memory layout (dynamic)
static constexpr int SM_WS = 0;                       // 512 floats (2 KB)
static constexpr int SM_A  = 2048;                    // 2 x 8 KB  (A int8, SW128)
static constexpr int SM_W  = 2048 + 2 * 8192;         // 2 x 64 KB (W int8, SW128)
static constexpr int SMEM_BYTES = SM_W + 2 * 65536;   // 149504

#define SMEM_SWIZZLE_128B(off) ((off) ^ (((off) >> 3) & 0x70))

// ---------------------------------------------------------------------------
// PTX helpers
// ---------------------------------------------------------------------------
__device__ __forceinline__ uint32_t smem_u32(const void* p) {
    uint32_t a;
    asm("{ .reg .u64 t; cvta.to.shared.u64 t, %1; cvt.u32.u64 %0, t; }"
        : "=r"(a) : "l"(p));
    return a;
}

#define CP_ASYNC_16(dst, src) \
    asm volatile("cp.async.cg.shared.global [%0], [%1], 16;" \
        :: "r"(dst), "l"(src))
#define CP_ASYNC_COMMIT() asm volatile("cp.async.commit_group;")
#define CP_ASYNC_WAIT0()  asm volatile("cp.async.wait_group 0;")

__device__ __forceinline__ void ldsm_x4(uint32_t& r0, uint32_t& r1,
                                        uint32_t& r2, uint32_t& r3,
                                        uint32_t addr) {
    asm volatile("ldmatrix.sync.aligned.m8n8.x4.shared.b16 {%0,%1,%2,%3}, [%4];"
        : "=r"(r0), "=r"(r1), "=r"(r2), "=r"(r3) : "r"(addr));
}

#define MMA_S8(d, a0, a1, a2, a3, b0, b1) \
    asm volatile("mma.sync.aligned.m16n8k32.row.col.s32.s8.s8.s32 " \
        "{%0,%1,%2,%3}, {%4,%5,%6,%7}, {%8,%9}, {%0,%1,%2,%3};" \
        : "+r"((d)[0]), "+r"((d)[1]), "+r"((d)[2]), "+r"((d)[3]) \
        : "r"(a0), "r"(a1), "r"(a2), "r"(a3), "r"(b0), "r"(b1))

// ---------------------------------------------------------------------------
// Global scratch
// ---------------------------------------------------------------------------
__device__ unsigned int g_maxabs = 0u;    // max|x| float bits (idempotent max)
__device__ int          g_w_oob  = 0;     // 1 => weight buffer is native int8
__device__ int8_t       g_wpack[N * K];   // canonical int8 weights (256 KB)

// ---------------------------------------------------------------------------
// Kernel 0a: detect weight dtype.
// Scan first N*K/4 32-bit words (256 KB; safe for both int8 and int32 buffers).
// If buffer holds int32 weights, every word is in [-128,127]. If it holds
// packed int8, words are arbitrary patterns -> some out of range.
// ---------------------------------------------------------------------------
__global__ __launch_bounds__(256) void wdetect_kernel(const int* __restrict__ w) {
    int i = blockIdx.x * blockDim.x + threadIdx.x;   // 0 .. N*K/4-1
    int v = w[i];
    bool oob = (unsigned)(v + 128) > 255u;
    unsigned mask = __ballot_sync(0xFFFFFFFFu, oob);
    if ((threadIdx.x & 31) == 0 && mask) atomicOr(&g_w_oob, 1);
}

// ---------------------------------------------------------------------------
// Kernel 0b: pack weights into canonical int8.
// int32 mode: 4 int32 -> 1 packed word. int8 mode: straight word copy.
// ---------------------------------------------------------------------------
__global__ __launch_bounds__(256) void wpack_kernel(const void* __restrict__ w) {
    int i = blockIdx.x * blockDim.x + threadIdx.x;   // 0 .. N*K/4-1
    uint32_t word;
    if (!g_w_oob) {
        int4 v = reinterpret_cast<const int4*>(w)[i];
        word = (uint32_t)(v.x & 0xFF) |
               ((uint32_t)(v.y & 0xFF) << 8) |
               ((uint32_t)(v.z & 0xFF) << 16) |
               ((uint32_t)v.w << 24);
    } else {
        word = reinterpret_cast<const uint32_t*>(w)[i];
    }
    reinterpret_cast<uint32_t*>(g_wpack)[i] = word;
}

// ---------------------------------------------------------------------------
// Kernel 1: max |x| reduction
// ---------------------------------------------------------------------------
__global__ __launch_bounds__(256) void maxabs_kernel(const float* __restrict__ x,
                                                     int n4) {
    float m = 0.0f;
    int stride = gridDim.x * blockDim.x;
    for (int i = blockIdx.x * blockDim.x + threadIdx.x; i < n4; i += stride) {
        float4 v = reinterpret_cast<const float4*>(x)[i];
        m = fmaxf(m, fmaxf(fmaxf(fabsf(v.x), fabsf(v.y)),
                           fmaxf(fabsf(v.z), fabsf(v.w))));
    }
    #pragma unroll
    for (int o = 16; o > 0; o >>= 1)
        m = fmaxf(m, __shfl_xor_sync(0xFFFFFFFFu, m, o));
    __shared__ float sm[8];
    if ((threadIdx.x & 31) == 0) sm[threadIdx.x >> 5] = m;
    __syncthreads();
    if (threadIdx.x < 32) {
        m = (threadIdx.x < (blockDim.x >> 5)) ? sm[threadIdx.x] : 0.0f;
        #pragma unroll
        for (int o = 4; o > 0; o >>= 1)
            m = fmaxf(m, __shfl_xor_sync(0xFFFFFFFFu, m, o));
        if (threadIdx.x == 0) atomicMax(&g_maxabs, __float_as_uint(m));
    }
}

// ---------------------------------------------------------------------------
// Kernel 2: fused quantize + int8 mma.sync GEMM + dequant epilogue
// CTA: 64 x 512 output tile. 16 warps = 2(M) x 8(N), warp tile 32 x 64.
// ---------------------------------------------------------------------------
__global__ __launch_bounds__(THREADS, 1)
void int8_gemm_kernel(const float* __restrict__ x,
                      const float* __restrict__ wscale,
                      float* __restrict__ out)
{
    extern __shared__ char smem[];
    uint32_t sb = smem_u32(smem);
    int tid  = threadIdx.x;
    int lane = tid & 31;
    int wid  = tid >> 5;
    int wm   = wid & 1;    // M group: rows wm*32
    int wn   = wid >> 1;   // N group: cols wn*64
    int m0   = blockIdx.x * BM;

    // stage weight scales
    for (int i = tid; i < N; i += THREADS)
        reinterpret_cast<float*>(smem + SM_WS)[i] = wscale[i];

    float mabs = __uint_as_float(g_maxabs);
    float xs   = fmaxf(mabs / 127.0f, 1e-5f);
    float inv  = 1.0f / xs;

    const int8_t* w = g_wpack;

    // ---- chunk loaders -----------------------------------------------------
    auto issue_w_cpasync = [&](int s, uint32_t wbuf) {
        #pragma unroll
        for (int it = 0; it < 8; it++) {
            int i = tid + it * THREADS;
            int n = i >> 3;
            int c = i & 7;
            const int8_t* src = w + (size_t)n * K + s * BK + c * 16;
            uint32_t off = SMEM_SWIZZLE_128B((uint32_t)(n * 128 + c * 16));
            CP_ASYNC_16(wbuf + off, src);
        }
        CP_ASYNC_COMMIT();
    };

    float4 xf[4];
    auto issue_x_ldg = [&](int s) {
        #pragma unroll
        for (int it = 0; it < 4; it++) {
            int i  = tid + it * THREADS;
            int r  = i >> 5;
            int c4 = i & 31;
            xf[it] = *reinterpret_cast<const float4*>(
                x + (size_t)(m0 + r) * K + s * BK + c4 * 4);
        }
    };
    auto quant_sts = [&](uint32_t abuf_off) {
        #pragma unroll
        for (int it = 0; it < 4; it++) {
            int i  = tid + it * THREADS;
            int r  = i >> 5;
            int c4 = i & 31;
            int q0 = min(127, max(-128, __float2int_rn(xf[it].x * inv)));
            int q1 = min(127, max(-128, __float2int_rn(xf[it].y * inv)));
            int q2 = min(127, max(-128, __float2int_rn(xf[it].z * inv)));
            int q3 = min(127, max(-128, __float2int_rn(xf[it].w * inv)));
            unsigned pk = (unsigned)(q0 & 0xFF) |
                          ((unsigned)(q1 & 0xFF) << 8) |
                          ((unsigned)(q2 & 0xFF) << 16) |
                          ((unsigned)q3 << 24);
            uint32_t off = SMEM_SWIZZLE_128B((uint32_t)(r * 128 + c4 * 4));
            *reinterpret_cast<uint32_t*>(smem + abuf_off + off) = pk;
        }
    };

    // ---- preload chunk 0 ---------------------------------------------------
    issue_w_cpasync(0, sb + SM_W);
    issue_x_ldg(0);
    quant_sts(SM_A);
    CP_ASYNC_WAIT0();
    __syncthreads();

    int acc[2][8][4];
    #pragma unroll
    for (int mt = 0; mt < 2; mt++)
        #pragma unroll
        for (int nt = 0; nt < 8; nt++)
            #pragma unroll
            for (int r = 0; r < 4; r++) acc[mt][nt][r] = 0;

    // per-lane ldmatrix address components
    int q  = lane >> 3;       // matrix index within x4
    int lr = lane & 7;        // row within matrix
    uint32_t axor = (uint32_t)lr * 16;
    // A: matrices q0=(rows+0,k0) q1=(rows+8,k0) q2=(rows+0,k16) q3=(rows+8,k16)
    uint32_t a_row_base = (uint32_t)(wm * 32 + (q & 1) * 8 + lr) * 128;
    uint32_t a_kpart    = (uint32_t)(q >> 1) * 16;
    // B: matrices q0=(tile+0,k0) q1=(tile+0,k16) q2=(tile+1,k0) q3=(tile+1,k16)
    uint32_t b_row_base = (uint32_t)((wn * 8 + (q >> 1)) * 8 + lr) * 128;
    uint32_t b_kpart    = (uint32_t)(q & 1) * 16;

    // ---- main loop ---------------------------------------------------------
    for (int s = 0; s < CHUNKS; s++) {
        int nb = (s + 1) & 1;
        if (s + 1 < CHUNKS) {
            issue_w_cpasync(s + 1, sb + SM_W + nb * 65536);
            issue_x_ldg(s + 1);
        }

        uint32_t aBase = sb + SM_A + (s & 1) * 8192;
        uint32_t wBase = sb + SM_W + (s & 1) * 65536;

        #pragma unroll
        for (int kk = 0; kk < 4; kk++) {
            uint32_t ak = ((uint32_t)(kk * 32) + a_kpart) ^ axor;
            uint32_t bk = ((uint32_t)(kk * 32) + b_kpart) ^ axor;

            uint32_t a0[4], a1[4];
            ldsm_x4(a0[0], a0[1], a0[2], a0[3], aBase + a_row_base + ak);
            ldsm_x4(a1[0], a1[1], a1[2], a1[3], aBase + a_row_base + 2048 + ak);

            #pragma unroll
            for (int tp = 0; tp < 4; tp++) {   // pairs of n-tiles
                uint32_t b[4];
                ldsm_x4(b[0], b[1], b[2], b[3],
                        wBase + b_row_base + (uint32_t)tp * 2048 + bk);
                MMA_S8(acc[0][tp * 2    ], a0[0], a0[1], a0[2], a0[3], b[0], b[1]);
                MMA_S8(acc[1][tp * 2    ], a1[0], a1[1], a1[2], a1[3], b[0], b[1]);
                MMA_S8(acc[0][tp * 2 + 1], a0[0], a0[1], a0[2], a0[3], b[2], b[3]);
                MMA_S8(acc[1][tp * 2 + 1], a1[0], a1[1], a1[2], a1[3], b[2], b[3]);
            }
        }

        if (s + 1 < CHUNKS) {
            quant_sts(SM_A + nb * 8192);
            CP_ASYNC_WAIT0();
            __syncthreads();
        }
    }

    // ---- epilogue: dequant + store ----------------------------------------
    const float* ws = reinterpret_cast<const float*>(smem + SM_WS);
    int g = lane >> 2;
    #pragma unroll
    for (int mt = 0; mt < 2; mt++) {
        int r0 = m0 + wm * 32 + mt * 16 + g;
        #pragma unroll
        for (int nt = 0; nt < 8; nt++) {
            int col = wn * 64 + nt * 8 + (lane & 3) * 2;
            float s0 = xs * ws[col];
            float s1 = xs * ws[col + 1];
            float2 v0, v1;
            v0.x = (float)acc[mt][nt][0] * s0;
            v0.y = (float)acc[mt][nt][1] * s1;
            v1.x = (float)acc[mt][nt][2] * s0;
            v1.y = (float)acc[mt][nt][3] * s1;
            *reinterpret_cast<float2*>(out + (size_t)r0 * N + col) = v0;
            *reinterpret_cast<float2*>(out + (size_t)(r0 + 8) * N + col) = v1;
        }
    }
}

// ---------------------------------------------------------------------------
// Launch
// ---------------------------------------------------------------------------
extern "C" void kernel_launch(void* const* d_in, const int* in_sizes, int n_in,
                              void* d_out, int out_size)
{
    const float* x   = (const float*)d_in[0];
    const void*  win = d_in[1];
    const float* ws  = (const float*)d_in[2];
    float* out = (float*)d_out;

    cudaFuncSetAttribute(int8_gemm_kernel,
                         cudaFuncAttributeMaxDynamicSharedMemorySize, SMEM_BYTES);

    wdetect_kernel<<<(N * K / 4) / 256, 256>>>((const int*)win);
    wpack_kernel<<<(N * K / 4) / 256, 256>>>(win);
    maxabs_kernel<<<1024, 256>>>(x, (M * K) / 4);
    int8_gemm_kernel<<<M / BM, THREADS, SMEM_BYTES>>>(x, ws, out);
}

// round 9
// speedup vs baseline: 1.3115x; 1.3115x over previous
#include <cuda_runtime.h>
#include <cstdint>

// ---------------------------------------------------------------------------
// Problem constants
// ---------------------------------------------------------------------------
static constexpr int M = 65536;
static constexpr int K = 512;
static constexpr int N = 512;

static constexpr int BM      = 64;       // CTA M tile
static constexpr int BK      = 128;      // K bytes per chunk
static constexpr int CHUNKS  = K / BK;   // 4
static constexpr int THREADS = 512;      // 16 warps: 8 tensor + 8 dp4a

// Shared memory layout (dynamic)
static constexpr int SM_WS = 0;                       // 512 floats (2 KB)
static constexpr int SM_A  = 2048;                    // 2 x 8 KB  (A int8, SW128)
static constexpr int SM_W  = 2048 + 2 * 8192;         // 2 x 64 KB (W int8, SW128)
static constexpr int SMEM_BYTES = SM_W + 2 * 65536;   // 149504

#define SMEM_SWIZZLE_128B(off) ((off) ^ (((off) >> 3) & 0x70))

// ---------------------------------------------------------------------------
// PTX helpers
// ---------------------------------------------------------------------------
__device__ __forceinline__ uint32_t smem_u32(const void* p) {
    uint32_t a;
    asm("{ .reg .u64 t; cvta.to.shared.u64 t, %1; cvt.u32.u64 %0, t; }"
        : "=r"(a) : "l"(p));
    return a;
}

#define CP_ASYNC_16(dst, src) \
    asm volatile("cp.async.cg.shared.global [%0], [%1], 16;" \
        :: "r"(dst), "l"(src))
#define CP_ASYNC_COMMIT() asm volatile("cp.async.commit_group;")
#define CP_ASYNC_WAIT0()  asm volatile("cp.async.wait_group 0;")

__device__ __forceinline__ void ldsm_x4(uint32_t& r0, uint32_t& r1,
                                        uint32_t& r2, uint32_t& r3,
                                        uint32_t addr) {
    asm volatile("ldmatrix.sync.aligned.m8n8.x4.shared.b16 {%0,%1,%2,%3}, [%4];"
        : "=r"(r0), "=r"(r1), "=r"(r2), "=r"(r3) : "r"(addr));
}

#define MMA_S8(d, a0, a1, a2, a3, b0, b1) \
    asm volatile("mma.sync.aligned.m16n8k32.row.col.s32.s8.s8.s32 " \
        "{%0,%1,%2,%3}, {%4,%5,%6,%7}, {%8,%9}, {%0,%1,%2,%3};" \
        : "+r"((d)[0]), "+r"((d)[1]), "+r"((d)[2]), "+r"((d)[3]) \
        : "r"(a0), "r"(a1), "r"(a2), "r"(a3), "r"(b0), "r"(b1))

// ---------------------------------------------------------------------------
// Global scratch
// ---------------------------------------------------------------------------
__device__ unsigned int g_maxabs = 0u;    // max|x| float bits (idempotent max)
__device__ int          g_w_oob  = 0;     // 1 => weight buffer is native int8
__device__ int8_t       g_wpack[N * K];   // canonical int8 weights (256 KB)

// ---------------------------------------------------------------------------
// Kernel 0a: detect weight dtype (int32 per element vs packed int8)
// ---------------------------------------------------------------------------
__global__ __launch_bounds__(256) void wdetect_kernel(const int* __restrict__ w) {
    int i = blockIdx.x * blockDim.x + threadIdx.x;   // 0 .. N*K/4-1
    int v = w[i];
    bool oob = (unsigned)(v + 128) > 255u;
    unsigned mask = __ballot_sync(0xFFFFFFFFu, oob);
    if ((threadIdx.x & 31) == 0 && mask) atomicOr(&g_w_oob, 1);
}

// ---------------------------------------------------------------------------
// Kernel 0b: pack weights into canonical int8
// ---------------------------------------------------------------------------
__global__ __launch_bounds__(256) void wpack_kernel(const void* __restrict__ w) {
    int i = blockIdx.x * blockDim.x + threadIdx.x;   // 0 .. N*K/4-1
    uint32_t word;
    if (!g_w_oob) {
        int4 v = reinterpret_cast<const int4*>(w)[i];
        word = (uint32_t)(v.x & 0xFF) |
               ((uint32_t)(v.y & 0xFF) << 8) |
               ((uint32_t)(v.z & 0xFF) << 16) |
               ((uint32_t)v.w << 24);
    } else {
        word = reinterpret_cast<const uint32_t*>(w)[i];
    }
    reinterpret_cast<uint32_t*>(g_wpack)[i] = word;
}

// ---------------------------------------------------------------------------
// Kernel 1: max |x| reduction
// ---------------------------------------------------------------------------
__global__ __launch_bounds__(256) void maxabs_kernel(const float* __restrict__ x,
                                                     int n4) {
    float m = 0.0f;
    int stride = gridDim.x * blockDim.x;
    for (int i = blockIdx.x * blockDim.x + threadIdx.x; i < n4; i += stride) {
        float4 v = reinterpret_cast<const float4*>(x)[i];
        m = fmaxf(m, fmaxf(fmaxf(fabsf(v.x), fabsf(v.y)),
                           fmaxf(fabsf(v.z), fabsf(v.w))));
    }
    #pragma unroll
    for (int o = 16; o > 0; o >>= 1)
        m = fmaxf(m, __shfl_xor_sync(0xFFFFFFFFu, m, o));
    __shared__ float sm[8];
    if ((threadIdx.x & 31) == 0) sm[threadIdx.x >> 5] = m;
    __syncthreads();
    if (threadIdx.x < 32) {
        m = (threadIdx.x < (blockDim.x >> 5)) ? sm[threadIdx.x] : 0.0f;
        #pragma unroll
        for (int o = 4; o > 0; o >>= 1)
            m = fmaxf(m, __shfl_xor_sync(0xFFFFFFFFu, m, o));
        if (threadIdx.x == 0) atomicMax(&g_maxabs, __float_as_uint(m));
    }
}

// ---------------------------------------------------------------------------
// Kernel 2: fused quantize + hybrid tensor/dp4a int8 GEMM + dequant epilogue
// CTA: 64 x 512 output tile.
//   warps 0-7  : mma.sync tensor path, N cols   0..255  (2M x 4N, 32x64 tiles)
//   warps 8-15 : dp4a ALU path,        N cols 256..511  (32 cols per warp)
// Both pipes run concurrently; legacy tensor peak (~157 TOPS) + dp4a (~136 TOPS).
// ---------------------------------------------------------------------------
__global__ __launch_bounds__(THREADS, 1)
void int8_gemm_kernel(const float* __restrict__ x,
                      const float* __restrict__ wscale,
                      float* __restrict__ out)
{
    extern __shared__ char smem[];
    uint32_t sb = smem_u32(smem);
    int tid  = threadIdx.x;
    int lane = tid & 31;
    int wid  = tid >> 5;
    int m0   = blockIdx.x * BM;

    // stage weight scales
    for (int i = tid; i < N; i += THREADS)
        reinterpret_cast<float*>(smem + SM_WS)[i] = wscale[i];

    float mabs = __uint_as_float(g_maxabs);
    float xs   = fmaxf(mabs / 127.0f, 1e-5f);
    float inv  = 1.0f / xs;

    const int8_t* w = g_wpack;

    // ---- chunk loaders (all 512 threads participate) -----------------------
    auto issue_w_cpasync = [&](int s, uint32_t wbuf) {
        #pragma unroll
        for (int it = 0; it < 8; it++) {
            int i = tid + it * THREADS;
            int n = i >> 3;
            int c = i & 7;
            const int8_t* src = w + (size_t)n * K + s * BK + c * 16;
            uint32_t off = SMEM_SWIZZLE_128B((uint32_t)(n * 128 + c * 16));
            CP_ASYNC_16(wbuf + off, src);
        }
        CP_ASYNC_COMMIT();
    };

    float4 xf[4];
    auto issue_x_ldg = [&](int s) {
        #pragma unroll
        for (int it = 0; it < 4; it++) {
            int i  = tid + it * THREADS;
            int r  = i >> 5;
            int c4 = i & 31;
            xf[it] = *reinterpret_cast<const float4*>(
                x + (size_t)(m0 + r) * K + s * BK + c4 * 4);
        }
    };
    auto quant_sts = [&](uint32_t abuf_off) {
        #pragma unroll
        for (int it = 0; it < 4; it++) {
            int i  = tid + it * THREADS;
            int r  = i >> 5;
            int c4 = i & 31;
            int q0 = min(127, max(-128, __float2int_rn(xf[it].x * inv)));
            int q1 = min(127, max(-128, __float2int_rn(xf[it].y * inv)));
            int q2 = min(127, max(-128, __float2int_rn(xf[it].z * inv)));
            int q3 = min(127, max(-128, __float2int_rn(xf[it].w * inv)));
            unsigned pk = (unsigned)(q0 & 0xFF) |
                          ((unsigned)(q1 & 0xFF) << 8) |
                          ((unsigned)(q2 & 0xFF) << 16) |
                          ((unsigned)q3 << 24);
            uint32_t off = SMEM_SWIZZLE_128B((uint32_t)(r * 128 + c4 * 4));
            *reinterpret_cast<uint32_t*>(smem + abuf_off + off) = pk;
        }
    };

    // ---- preload chunk 0 ---------------------------------------------------
    issue_w_cpasync(0, sb + SM_W);
    issue_x_ldg(0);
    quant_sts(SM_A);
    CP_ASYNC_WAIT0();
    __syncthreads();

    const float* wsp = reinterpret_cast<const float*>(smem + SM_WS);

    if (wid < 8) {
        // =================== TENSOR PATH (cols 0..255) ======================
        int wm = wid & 1;     // rows wm*32
        int wn = wid >> 1;    // cols wn*64 (0..3)

        int acc[2][8][4];
        #pragma unroll
        for (int mt = 0; mt < 2; mt++)
            #pragma unroll
            for (int nt = 0; nt < 8; nt++)
                #pragma unroll
                for (int r = 0; r < 4; r++) acc[mt][nt][r] = 0;

        int q  = lane >> 3;
        int lr = lane & 7;
        uint32_t axor = (uint32_t)lr * 16;
        uint32_t a_row_base = (uint32_t)(wm * 32 + (q & 1) * 8 + lr) * 128;
        uint32_t a_kpart    = (uint32_t)(q >> 1) * 16;
        uint32_t b_row_base = (uint32_t)((wn * 8 + (q >> 1)) * 8 + lr) * 128;
        uint32_t b_kpart    = (uint32_t)(q & 1) * 16;

        for (int s = 0; s < CHUNKS; s++) {
            int nb = (s + 1) & 1;
            if (s + 1 < CHUNKS) {
                issue_w_cpasync(s + 1, sb + SM_W + nb * 65536);
                issue_x_ldg(s + 1);
            }

            uint32_t aBase = sb + SM_A + (s & 1) * 8192;
            uint32_t wBase = sb + SM_W + (s & 1) * 65536;

            #pragma unroll
            for (int kk = 0; kk < 4; kk++) {
                uint32_t ak = ((uint32_t)(kk * 32) + a_kpart) ^ axor;
                uint32_t bk = ((uint32_t)(kk * 32) + b_kpart) ^ axor;

                uint32_t a0[4], a1[4];
                ldsm_x4(a0[0], a0[1], a0[2], a0[3], aBase + a_row_base + ak);
                ldsm_x4(a1[0], a1[1], a1[2], a1[3], aBase + a_row_base + 2048 + ak);

                #pragma unroll
                for (int tp = 0; tp < 4; tp++) {
                    uint32_t b[4];
                    ldsm_x4(b[0], b[1], b[2], b[3],
                            wBase + b_row_base + (uint32_t)tp * 2048 + bk);
                    MMA_S8(acc[0][tp * 2    ], a0[0], a0[1], a0[2], a0[3], b[0], b[1]);
                    MMA_S8(acc[1][tp * 2    ], a1[0], a1[1], a1[2], a1[3], b[0], b[1]);
                    MMA_S8(acc[0][tp * 2 + 1], a0[0], a0[1], a0[2], a0[3], b[2], b[3]);
                    MMA_S8(acc[1][tp * 2 + 1], a1[0], a1[1], a1[2], a1[3], b[2], b[3]);
                }
            }

            if (s + 1 < CHUNKS) {
                quant_sts(SM_A + nb * 8192);
                CP_ASYNC_WAIT0();
                __syncthreads();
            }
        }

        // epilogue
        int g = lane >> 2;
        #pragma unroll
        for (int mt = 0; mt < 2; mt++) {
            int r0 = m0 + wm * 32 + mt * 16 + g;
            #pragma unroll
            for (int nt = 0; nt < 8; nt++) {
                int col = wn * 64 + nt * 8 + (lane & 3) * 2;
                float s0 = xs * wsp[col];
                float s1 = xs * wsp[col + 1];
                float2 v0, v1;
                v0.x = (float)acc[mt][nt][0] * s0;
                v0.y = (float)acc[mt][nt][1] * s1;
                v1.x = (float)acc[mt][nt][2] * s0;
                v1.y = (float)acc[mt][nt][3] * s1;
                *reinterpret_cast<float2*>(out + (size_t)r0 * N + col) = v0;
                *reinterpret_cast<float2*>(out + (size_t)(r0 + 8) * N + col) = v1;
            }
        }
    } else {
        // =================== DP4A PATH (cols 256..511) ======================
        int dw = wid - 8;           // 0..7, cols 256 + dw*32 .. +32
        int rg = lane & 7;          // row group: rows rg + 8i
        int cg = lane >> 3;         // col group: cols cg + 4j (within warp's 32)
        int cbase = 256 + dw * 32;

        int acc[8][8];
        #pragma unroll
        for (int i = 0; i < 8; i++)
            #pragma unroll
            for (int j = 0; j < 8; j++) acc[i][j] = 0;

        // A row rg+8i: (row&7)==rg -> swizzle XOR = rg<<4 on k-offset
        // B col c = cbase+cg+4j: (c&7) = cg+4*(j&1) -> per-parity XOR
        uint32_t aRowOff = (uint32_t)rg * 128;
        uint32_t bRowOff = (uint32_t)(cbase + cg) * 128;
        uint32_t aswz  = (uint32_t)rg << 4;
        uint32_t cswz0 = (uint32_t)cg << 4;
        uint32_t cswz1 = (uint32_t)(cg + 4) << 4;

        for (int s = 0; s < CHUNKS; s++) {
            int nb = (s + 1) & 1;
            if (s + 1 < CHUNKS) {
                issue_w_cpasync(s + 1, sb + SM_W + nb * 65536);
                issue_x_ldg(s + 1);
            }

            uint32_t aB = SM_A + (uint32_t)(s & 1) * 8192 + aRowOff;
            uint32_t bB = SM_W + (uint32_t)(s & 1) * 65536 + bRowOff;

            #pragma unroll 1
            for (int kw = 0; kw < 128; kw += 8) {
                uint32_t ka = (uint32_t)kw ^ aswz;
                int2 A[8];
                #pragma unroll
                for (int i = 0; i < 8; i++)
                    A[i] = *reinterpret_cast<const int2*>(
                        smem + aB + (uint32_t)i * 1024 + ka);
                int2 B[8];
                #pragma unroll
                for (int j = 0; j < 8; j++) {
                    uint32_t kb = (uint32_t)kw ^ ((j & 1) ? cswz1 : cswz0);
                    B[j] = *reinterpret_cast<const int2*>(
                        smem + bB + (uint32_t)j * 512 + kb);
                }
                #pragma unroll
                for (int i = 0; i < 8; i++)
                    #pragma unroll
                    for (int j = 0; j < 8; j++) {
                        acc[i][j] = __dp4a(A[i].x, B[j].x, acc[i][j]);
                        acc[i][j] = __dp4a(A[i].y, B[j].y, acc[i][j]);
                    }
            }

            if (s + 1 < CHUNKS) {
                quant_sts(SM_A + nb * 8192);
                CP_ASYNC_WAIT0();
                __syncthreads();
            }
        }

        // epilogue: dequant, transpose through (now free) W buffer 0 for
        // coalesced stores. Scratch: 64 rows x 128B per warp.
        uint32_t scr = SM_W + (uint32_t)dw * 8192;
        #pragma unroll
        for (int i = 0; i < 8; i++) {
            int r = rg + 8 * i;
            uint32_t roff = scr + (uint32_t)r * 128;
            uint32_t rswz = (uint32_t)rg << 4;   // (r&7)==rg
            #pragma unroll
            for (int j = 0; j < 8; j++) {
                int c = cg + 4 * j;
                float v = (float)acc[i][j] * (xs * wsp[cbase + c]);
                *reinterpret_cast<float*>(
                    smem + roff + (((uint32_t)c * 4) ^ rswz)) = v;
            }
        }
        __syncwarp();
        #pragma unroll 4
        for (int r = 0; r < 64; r++) {
            uint32_t off = (uint32_t)r * 128 +
                           (((uint32_t)lane * 4) ^ (((uint32_t)(r & 7)) << 4));
            float v = *reinterpret_cast<const float*>(smem + scr + off);
            out[(size_t)(m0 + r) * N + cbase + lane] = v;
        }
    }
}

// ---------------------------------------------------------------------------
// Launch
// ---------------------------------------------------------------------------
extern "C" void kernel_launch(void* const* d_in, const int* in_sizes, int n_in,
                              void* d_out, int out_size)
{
    const float* x   = (const float*)d_in[0];
    const void*  win = d_in[1];
    const float* ws  = (const float*)d_in[2];
    float* out = (float*)d_out;

    cudaFuncSetAttribute(int8_gemm_kernel,
                         cudaFuncAttributeMaxDynamicSharedMemorySize, SMEM_BYTES);

    wdetect_kernel<<<(N * K / 4) / 256, 256>>>((const int*)win);
    wpack_kernel<<<(N * K / 4) / 256, 256>>>(win);
    maxabs_kernel<<<1024, 256>>>(x, (M * K) / 4);
    int8_gemm_kernel<<<M / BM, THREADS, SMEM_BYTES>>>(x, ws, out);
}